// round 2
// baseline (speedup 1.0000x reference)
#include <cuda_runtime.h>
#include <cstdint>

#define D_MODEL 1024
#define N_HEADS 16
#define D_HEAD  64
#define BATCH   4
#define SEQ     2048
#define M_TOT   (BATCH * SEQ)   // 8192

// Scratch (device globals: allocation-free per harness rules)
__device__ float g_Q[(size_t)BATCH * N_HEADS * SEQ * D_HEAD];   // [b,h,s,dh]
__device__ float g_K[(size_t)BATCH * N_HEADS * SEQ * D_HEAD];
__device__ float g_V[(size_t)BATCH * N_HEADS * SEQ * D_HEAD];
__device__ float g_ctx[(size_t)M_TOT * D_MODEL];                // [b*s, d]

// ---------------------------------------------------------------------------
// Tiled fp32 GEMM core: C_tile(128x128) += A(128xK) * W(Kx128), K = 1024.
// 256 threads, each computes an 8x8 register tile. A is staged transposed.
// ---------------------------------------------------------------------------
__device__ __forceinline__ void gemm_tile_128x128(
    const float* __restrict__ A,   // [M, 1024] row-major
    const float* __restrict__ W,   // [1024, 1024] row-major
    float acc[8][8], int bm, int bn)
{
    __shared__ float As[16][132];  // +4 pad
    __shared__ float Bs[16][128];

    const int tid = threadIdx.x;
    const int ty = tid >> 4;       // 0..15
    const int tx = tid & 15;       // 0..15

    for (int k0 = 0; k0 < 1024; k0 += 16) {
        // Stage A tile (128 rows x 16 k) transposed into As[k][m]
        #pragma unroll
        for (int i = 0; i < 2; i++) {
            int f  = tid + (i << 8);          // 0..511 float4 slots
            int am = f >> 2;                  // 0..127
            int ak = (f & 3) << 2;            // 0,4,8,12
            float4 v = *reinterpret_cast<const float4*>(
                &A[(size_t)(bm + am) * 1024 + k0 + ak]);
            As[ak + 0][am] = v.x;
            As[ak + 1][am] = v.y;
            As[ak + 2][am] = v.z;
            As[ak + 3][am] = v.w;
        }
        // Stage W tile (16 k x 128 n)
        #pragma unroll
        for (int i = 0; i < 2; i++) {
            int f   = tid + (i << 8);
            int bk  = f >> 5;                 // 0..15
            int bn4 = (f & 31) << 2;          // 0..124
            *reinterpret_cast<float4*>(&Bs[bk][bn4]) =
                *reinterpret_cast<const float4*>(
                    &W[(size_t)(k0 + bk) * 1024 + bn + bn4]);
        }
        __syncthreads();

        #pragma unroll
        for (int k = 0; k < 16; k++) {
            float4 a0 = *reinterpret_cast<const float4*>(&As[k][ty * 8]);
            float4 a1 = *reinterpret_cast<const float4*>(&As[k][ty * 8 + 4]);
            float4 b0 = *reinterpret_cast<const float4*>(&Bs[k][tx * 8]);
            float4 b1 = *reinterpret_cast<const float4*>(&Bs[k][tx * 8 + 4]);
            float a[8] = {a0.x, a0.y, a0.z, a0.w, a1.x, a1.y, a1.z, a1.w};
            float b[8] = {b0.x, b0.y, b0.z, b0.w, b1.x, b1.y, b1.z, b1.w};
            #pragma unroll
            for (int i = 0; i < 8; i++)
                #pragma unroll
                for (int j = 0; j < 8; j++)
                    acc[i][j] += a[i] * b[j];
        }
        __syncthreads();
    }
}

// ---------------------------------------------------------------------------
// QKV projection: out = x @ W_{q,k,v} + b, written in [b,h,s,dh] layout.
// grid = (M/128, N/128, 3), z selects Q/K/V.
// ---------------------------------------------------------------------------
__global__ __launch_bounds__(256, 2)
void qkv_gemm_kernel(const float* __restrict__ x,
                     const float* __restrict__ Wq, const float* __restrict__ bq,
                     const float* __restrict__ Wk, const float* __restrict__ bk,
                     const float* __restrict__ Wv, const float* __restrict__ bv)
{
    const float* W; const float* bias; float* out;
    if      (blockIdx.z == 0) { W = Wq; bias = bq; out = g_Q; }
    else if (blockIdx.z == 1) { W = Wk; bias = bk; out = g_K; }
    else                      { W = Wv; bias = bv; out = g_V; }

    const int bm = blockIdx.x * 128;
    const int bn = blockIdx.y * 128;

    float acc[8][8];
    #pragma unroll
    for (int i = 0; i < 8; i++)
        #pragma unroll
        for (int j = 0; j < 8; j++) acc[i][j] = 0.f;

    gemm_tile_128x128(x, W, acc, bm, bn);

    const int ty = threadIdx.x >> 4;
    const int tx = threadIdx.x & 15;

    #pragma unroll
    for (int i = 0; i < 8; i++) {
        int m = bm + ty * 8 + i;
        int b = m >> 11;                 // /SEQ
        int s = m & (SEQ - 1);
        // cols tx*8 .. tx*8+7 all fall inside one head (8 | 64)
        int n0 = bn + tx * 8;
        int h  = n0 >> 6;
        int dh = n0 & 63;
        float* dst = &out[(((size_t)(b * N_HEADS + h) * SEQ + s) * D_HEAD) + dh];
        float4 v0 = make_float4(acc[i][0] + bias[n0 + 0], acc[i][1] + bias[n0 + 1],
                                acc[i][2] + bias[n0 + 2], acc[i][3] + bias[n0 + 3]);
        float4 v1 = make_float4(acc[i][4] + bias[n0 + 4], acc[i][5] + bias[n0 + 5],
                                acc[i][6] + bias[n0 + 6], acc[i][7] + bias[n0 + 7]);
        *reinterpret_cast<float4*>(dst)     = v0;
        *reinterpret_cast<float4*>(dst + 4) = v1;
    }
}

// ---------------------------------------------------------------------------
// Causal flash attention, fp32, online softmax.
// Block = 128 threads; 64 Q rows per block (2 threads per row, each owns
// 32 of the 64 head dims). KV tiles of 32 rows staged in smem.
// grid = (SEQ/64, BATCH*N_HEADS)
// ---------------------------------------------------------------------------
__global__ __launch_bounds__(128, 3)
void flash_attn_kernel()
{
    __shared__ float Ks[32][64];
    __shared__ float Vs[32][64];

    const int tid  = threadIdx.x;
    const int qt   = blockIdx.x;                 // 0..31
    const int bh   = blockIdx.y;                 // 0..63
    const int row  = (qt << 6) + (tid >> 1);     // global q index
    const int half = tid & 1;                    // which 32 dims

    const float sc = 0.125f * 1.44269504088896340736f;  // 1/sqrt(64) * log2(e)

    const float* qptr = &g_Q[((size_t)bh * SEQ + row) * D_HEAD + half * 32];
    float q[32];
    #pragma unroll
    for (int i = 0; i < 32; i += 4) {
        float4 v = *reinterpret_cast<const float4*>(&qptr[i]);
        q[i] = v.x * sc; q[i+1] = v.y * sc; q[i+2] = v.z * sc; q[i+3] = v.w * sc;
    }

    float mval = -1e30f, lval = 0.f;
    float acc[32];
    #pragma unroll
    for (int i = 0; i < 32; i++) acc[i] = 0.f;

    const float* Kbase = &g_K[(size_t)bh * SEQ * D_HEAD];
    const float* Vbase = &g_V[(size_t)bh * SEQ * D_HEAD];

    const int ntiles = 2 * qt + 2;               // causal: k up to qt*64+63
    for (int t = 0; t < ntiles; t++) {
        // Stage 32x64 K and V tiles (2048 floats each)
        const float* ksrc = Kbase + (size_t)t * 32 * D_HEAD;
        const float* vsrc = Vbase + (size_t)t * 32 * D_HEAD;
        #pragma unroll
        for (int i = 0; i < 4; i++) {
            int f = (tid + (i << 7)) << 2;        // float offset 0..2044
            *reinterpret_cast<float4*>(&Ks[0][0] + f) =
                *reinterpret_cast<const float4*>(ksrc + f);
            *reinterpret_cast<float4*>(&Vs[0][0] + f) =
                *reinterpret_cast<const float4*>(vsrc + f);
        }
        __syncthreads();

        float s[32];
        #pragma unroll
        for (int j = 0; j < 32; j++) {
            float sum = 0.f;
            #pragma unroll
            for (int d = 0; d < 32; d += 4) {
                float4 kv = *reinterpret_cast<const float4*>(&Ks[j][half * 32 + d]);
                sum += q[d] * kv.x + q[d+1] * kv.y + q[d+2] * kv.z + q[d+3] * kv.w;
            }
            sum += __shfl_xor_sync(0xffffffffu, sum, 1);
            s[j] = sum;
        }

        if (t * 32 + 31 > row) {                  // diagonal tile: mask
            #pragma unroll
            for (int j = 0; j < 32; j++)
                if (t * 32 + j > row) s[j] = -1e30f;
        }

        float mt = mval;
        #pragma unroll
        for (int j = 0; j < 32; j++) mt = fmaxf(mt, s[j]);
        float alpha = exp2f(mval - mt);
        mval = mt;

        float ls = 0.f;
        #pragma unroll
        for (int j = 0; j < 32; j++) {
            s[j] = exp2f(s[j] - mt);
            ls += s[j];
        }
        lval = lval * alpha + ls;

        #pragma unroll
        for (int d = 0; d < 32; d++) acc[d] *= alpha;

        #pragma unroll
        for (int j = 0; j < 32; j++) {
            float p = s[j];
            #pragma unroll
            for (int d = 0; d < 32; d += 4) {
                float4 vv = *reinterpret_cast<const float4*>(&Vs[j][half * 32 + d]);
                acc[d]   += p * vv.x;
                acc[d+1] += p * vv.y;
                acc[d+2] += p * vv.z;
                acc[d+3] += p * vv.w;
            }
        }
        __syncthreads();
    }

    // Write context back in [b*s, d_model] layout
    const int b = bh >> 4;
    const int h = bh & 15;
    const float inv = 1.f / lval;
    float* optr = &g_ctx[((size_t)(b * SEQ + row)) * D_MODEL + h * D_HEAD + half * 32];
    #pragma unroll
    for (int d = 0; d < 32; d += 4) {
        float4 v = make_float4(acc[d] * inv, acc[d+1] * inv, acc[d+2] * inv, acc[d+3] * inv);
        *reinterpret_cast<float4*>(&optr[d]) = v;
    }
}

// ---------------------------------------------------------------------------
// Output projection: out = ctx @ W_o + b_o   (plain row-major)
// ---------------------------------------------------------------------------
__global__ __launch_bounds__(256, 2)
void out_gemm_kernel(const float* __restrict__ Wo,
                     const float* __restrict__ bo,
                     float* __restrict__ out)
{
    const int bm = blockIdx.x * 128;
    const int bn = blockIdx.y * 128;

    float acc[8][8];
    #pragma unroll
    for (int i = 0; i < 8; i++)
        #pragma unroll
        for (int j = 0; j < 8; j++) acc[i][j] = 0.f;

    gemm_tile_128x128(g_ctx, Wo, acc, bm, bn);

    const int ty = threadIdx.x >> 4;
    const int tx = threadIdx.x & 15;

    #pragma unroll
    for (int i = 0; i < 8; i++) {
        int m  = bm + ty * 8 + i;
        int n0 = bn + tx * 8;
        float* dst = &out[(size_t)m * D_MODEL + n0];
        float4 v0 = make_float4(acc[i][0] + bo[n0 + 0], acc[i][1] + bo[n0 + 1],
                                acc[i][2] + bo[n0 + 2], acc[i][3] + bo[n0 + 3]);
        float4 v1 = make_float4(acc[i][4] + bo[n0 + 4], acc[i][5] + bo[n0 + 5],
                                acc[i][6] + bo[n0 + 6], acc[i][7] + bo[n0 + 7]);
        *reinterpret_cast<float4*>(dst)     = v0;
        *reinterpret_cast<float4*>(dst + 4) = v1;
    }
}

// ---------------------------------------------------------------------------
extern "C" void kernel_launch(void* const* d_in, const int* in_sizes, int n_in,
                              void* d_out, int out_size)
{
    const float* x   = (const float*)d_in[0];
    const float* W_q = (const float*)d_in[1];
    const float* b_q = (const float*)d_in[2];
    const float* W_k = (const float*)d_in[3];
    const float* b_k = (const float*)d_in[4];
    const float* W_v = (const float*)d_in[5];
    const float* b_v = (const float*)d_in[6];
    const float* W_o = (const float*)d_in[7];
    const float* b_o = (const float*)d_in[8];
    float* out = (float*)d_out;

    dim3 gProj(M_TOT / 128, D_MODEL / 128, 3);
    qkv_gemm_kernel<<<gProj, 256>>>(x, W_q, b_q, W_k, b_k, W_v, b_v);

    dim3 gAttn(SEQ / 64, BATCH * N_HEADS);
    flash_attn_kernel<<<gAttn, 128>>>();

    dim3 gOut(M_TOT / 128, D_MODEL / 128);
    out_gemm_kernel<<<gOut, 256>>>(W_o, b_o, out);
}

// round 4
// speedup vs baseline: 1.2765x; 1.2765x over previous
#include <cuda_runtime.h>
#include <cstdint>

#define D_MODEL 1024
#define N_HEADS 16
#define D_HEAD  64
#define BATCH   4
#define SEQ     2048
#define M_TOT   (BATCH * SEQ)   // 8192

// Scratch (device globals: allocation-free per harness rules)
__device__ float g_Q[(size_t)BATCH * N_HEADS * SEQ * D_HEAD];   // [b,h,s,dh]
__device__ float g_K[(size_t)BATCH * N_HEADS * SEQ * D_HEAD];
__device__ float g_V[(size_t)BATCH * N_HEADS * SEQ * D_HEAD];
__device__ float g_ctx[(size_t)M_TOT * D_MODEL];                // [b*s, d]

// ---------------------------------------------------------------------------
// tf32 helpers
// ---------------------------------------------------------------------------
__device__ __forceinline__ uint32_t f2tf32(float f) {
    uint32_t u;
    asm("cvt.rna.tf32.f32 %0, %1;" : "=r"(u) : "f"(f));
    return u;
}

__device__ __forceinline__ void mma_tf32_16x8x8(
    float c[4], const uint32_t a[4], const uint32_t b[2])
{
    asm volatile(
        "mma.sync.aligned.m16n8k8.row.col.f32.tf32.tf32.f32 "
        "{%0,%1,%2,%3}, {%4,%5,%6,%7}, {%8,%9}, {%0,%1,%2,%3};"
        : "+f"(c[0]), "+f"(c[1]), "+f"(c[2]), "+f"(c[3])
        : "r"(a[0]), "r"(a[1]), "r"(a[2]), "r"(a[3]),
          "r"(b[0]), "r"(b[1]));
}

// ---------------------------------------------------------------------------
// tf32 tensor-core GEMM core: C_tile(128x128) = A(128xK) * W(Kx128), K=1024.
// 256 threads = 8 warps in 2(M) x 4(N); each warp computes 64x32 via
// 4x4 m16n8k8 mma fragments. Smem strides (20, 136) are bank-conflict-free
// for the fragment load patterns.
// ---------------------------------------------------------------------------
#define A_STRIDE 20
#define B_STRIDE 136

__device__ __forceinline__ void gemm_tf32_core(
    const float* __restrict__ A,   // [M, 1024] row-major
    const float* __restrict__ W,   // [1024, 1024] row-major
    float acc[4][4][4], int bm, int bn)
{
    __shared__ __align__(16) float As[128][A_STRIDE];  // [m][k]
    __shared__ __align__(16) float Bs[16][B_STRIDE];   // [k][n]

    const int tid    = threadIdx.x;
    const int warp   = tid >> 5;
    const int lane   = tid & 31;
    const int gID    = lane >> 2;     // 0..7
    const int tID    = lane & 3;      // 0..3
    const int m_warp = (warp & 1) * 64;
    const int n_warp = (warp >> 1) * 32;

    for (int k0 = 0; k0 < 1024; k0 += 16) {
        // Stage A tile: 128 rows x 16 k (512 float4, 2 per thread)
        #pragma unroll
        for (int i = 0; i < 2; i++) {
            int f   = tid * 2 + i;            // 0..511
            int row = f >> 2;                 // 0..127
            int kc  = (f & 3) << 2;           // 0,4,8,12
            float4 v = *reinterpret_cast<const float4*>(
                &A[(size_t)(bm + row) * 1024 + k0 + kc]);
            *reinterpret_cast<float4*>(&As[row][kc]) = v;
        }
        // Stage B tile: 16 k x 128 n
        #pragma unroll
        for (int i = 0; i < 2; i++) {
            int f   = tid * 2 + i;
            int row = f >> 5;                 // 0..15
            int nc  = (f & 31) << 2;          // 0..124
            float4 v = *reinterpret_cast<const float4*>(
                &W[(size_t)(k0 + row) * 1024 + bn + nc]);
            *reinterpret_cast<float4*>(&Bs[row][nc]) = v;
        }
        __syncthreads();

        #pragma unroll
        for (int ks = 0; ks < 16; ks += 8) {
            // A fragments: 4 M-tiles
            uint32_t afrag[4][4];
            #pragma unroll
            for (int i = 0; i < 4; i++) {
                int r0 = m_warp + i * 16 + gID;
                afrag[i][0] = f2tf32(As[r0    ][ks + tID    ]);
                afrag[i][1] = f2tf32(As[r0 + 8][ks + tID    ]);
                afrag[i][2] = f2tf32(As[r0    ][ks + tID + 4]);
                afrag[i][3] = f2tf32(As[r0 + 8][ks + tID + 4]);
            }
            // B fragments: 4 N-tiles
            uint32_t bfrag[4][2];
            #pragma unroll
            for (int j = 0; j < 4; j++) {
                int c0 = n_warp + j * 8 + gID;
                bfrag[j][0] = f2tf32(Bs[ks + tID    ][c0]);
                bfrag[j][1] = f2tf32(Bs[ks + tID + 4][c0]);
            }
            #pragma unroll
            for (int i = 0; i < 4; i++)
                #pragma unroll
                for (int j = 0; j < 4; j++)
                    mma_tf32_16x8x8(acc[i][j], afrag[i], bfrag[j]);
        }
        __syncthreads();
    }
}

// ---------------------------------------------------------------------------
// QKV projection: out = x @ W_{q,k,v} + b, written in [b,h,s,dh] layout.
// grid = (M/128, N/128, 3), z selects Q/K/V.
// ---------------------------------------------------------------------------
__global__ __launch_bounds__(256, 2)
void qkv_gemm_kernel(const float* __restrict__ x,
                     const float* __restrict__ Wq, const float* __restrict__ bq,
                     const float* __restrict__ Wk, const float* __restrict__ bk,
                     const float* __restrict__ Wv, const float* __restrict__ bv)
{
    const float* W; const float* bias; float* out;
    if      (blockIdx.z == 0) { W = Wq; bias = bq; out = g_Q; }
    else if (blockIdx.z == 1) { W = Wk; bias = bk; out = g_K; }
    else                      { W = Wv; bias = bv; out = g_V; }

    const int bm = blockIdx.x * 128;
    const int bn = blockIdx.y * 128;

    float acc[4][4][4];
    #pragma unroll
    for (int i = 0; i < 4; i++)
        #pragma unroll
        for (int j = 0; j < 4; j++)
            #pragma unroll
            for (int r = 0; r < 4; r++) acc[i][j][r] = 0.f;

    gemm_tf32_core(x, W, acc, bm, bn);

    const int warp   = threadIdx.x >> 5;
    const int lane   = threadIdx.x & 31;
    const int gID    = lane >> 2;
    const int tID    = lane & 3;
    const int m_warp = (warp & 1) * 64;
    const int n_warp = (warp >> 1) * 32;

    #pragma unroll
    for (int i = 0; i < 4; i++) {
        #pragma unroll
        for (int j = 0; j < 4; j++) {
            int n0 = bn + n_warp + j * 8 + tID * 2;
            int h  = n0 >> 6;
            int dh = n0 & 63;
            float b0v = bias[n0], b1v = bias[n0 + 1];
            #pragma unroll
            for (int rr = 0; rr < 2; rr++) {
                int m = bm + m_warp + i * 16 + gID + rr * 8;
                int b = m >> 11;
                int s = m & (SEQ - 1);
                float* dst = &out[(((size_t)(b * N_HEADS + h) * SEQ + s) * D_HEAD) + dh];
                float2 v = make_float2(acc[i][j][rr * 2] + b0v,
                                       acc[i][j][rr * 2 + 1] + b1v);
                *reinterpret_cast<float2*>(dst) = v;
            }
        }
    }
}

// ---------------------------------------------------------------------------
// Output projection: out = ctx @ W_o + b_o   (row-major [M, D])
// ---------------------------------------------------------------------------
__global__ __launch_bounds__(256, 2)
void out_gemm_kernel(const float* __restrict__ Wo,
                     const float* __restrict__ bo,
                     float* __restrict__ out)
{
    const int bm = blockIdx.x * 128;
    const int bn = blockIdx.y * 128;

    float acc[4][4][4];
    #pragma unroll
    for (int i = 0; i < 4; i++)
        #pragma unroll
        for (int j = 0; j < 4; j++)
            #pragma unroll
            for (int r = 0; r < 4; r++) acc[i][j][r] = 0.f;

    gemm_tf32_core(g_ctx, Wo, acc, bm, bn);

    const int warp   = threadIdx.x >> 5;
    const int lane   = threadIdx.x & 31;
    const int gID    = lane >> 2;
    const int tID    = lane & 3;
    const int m_warp = (warp & 1) * 64;
    const int n_warp = (warp >> 1) * 32;

    #pragma unroll
    for (int i = 0; i < 4; i++) {
        #pragma unroll
        for (int j = 0; j < 4; j++) {
            int n0 = bn + n_warp + j * 8 + tID * 2;
            float b0v = bo[n0], b1v = bo[n0 + 1];
            #pragma unroll
            for (int rr = 0; rr < 2; rr++) {
                int m = bm + m_warp + i * 16 + gID + rr * 8;
                float2 v = make_float2(acc[i][j][rr * 2] + b0v,
                                       acc[i][j][rr * 2 + 1] + b1v);
                *reinterpret_cast<float2*>(&out[(size_t)m * D_MODEL + n0]) = v;
            }
        }
    }
}

// ---------------------------------------------------------------------------
// Causal flash attention, fp32, online softmax (unchanged from R2).
// Block = 128 threads; 64 Q rows per block (2 threads per row, each owns
// 32 of the 64 head dims). KV tiles of 32 rows staged in smem.
// grid = (SEQ/64, BATCH*N_HEADS)
// ---------------------------------------------------------------------------
__global__ __launch_bounds__(128, 3)
void flash_attn_kernel()
{
    __shared__ float Ks[32][64];
    __shared__ float Vs[32][64];

    const int tid  = threadIdx.x;
    const int qt   = blockIdx.x;                 // 0..31
    const int bh   = blockIdx.y;                 // 0..63
    const int row  = (qt << 6) + (tid >> 1);     // global q index
    const int half = tid & 1;                    // which 32 dims

    const float sc = 0.125f * 1.44269504088896340736f;  // 1/sqrt(64) * log2(e)

    const float* qptr = &g_Q[((size_t)bh * SEQ + row) * D_HEAD + half * 32];
    float q[32];
    #pragma unroll
    for (int i = 0; i < 32; i += 4) {
        float4 v = *reinterpret_cast<const float4*>(&qptr[i]);
        q[i] = v.x * sc; q[i+1] = v.y * sc; q[i+2] = v.z * sc; q[i+3] = v.w * sc;
    }

    float mval = -1e30f, lval = 0.f;
    float acc[32];
    #pragma unroll
    for (int i = 0; i < 32; i++) acc[i] = 0.f;

    const float* Kbase = &g_K[(size_t)bh * SEQ * D_HEAD];
    const float* Vbase = &g_V[(size_t)bh * SEQ * D_HEAD];

    const int ntiles = 2 * qt + 2;               // causal: k up to qt*64+63
    for (int t = 0; t < ntiles; t++) {
        const float* ksrc = Kbase + (size_t)t * 32 * D_HEAD;
        const float* vsrc = Vbase + (size_t)t * 32 * D_HEAD;
        #pragma unroll
        for (int i = 0; i < 4; i++) {
            int f = (tid + (i << 7)) << 2;        // float offset 0..2044
            *reinterpret_cast<float4*>(&Ks[0][0] + f) =
                *reinterpret_cast<const float4*>(ksrc + f);
            *reinterpret_cast<float4*>(&Vs[0][0] + f) =
                *reinterpret_cast<const float4*>(vsrc + f);
        }
        __syncthreads();

        float s[32];
        #pragma unroll
        for (int j = 0; j < 32; j++) {
            float sum = 0.f;
            #pragma unroll
            for (int d = 0; d < 32; d += 4) {
                float4 kv = *reinterpret_cast<const float4*>(&Ks[j][half * 32 + d]);
                sum += q[d] * kv.x + q[d+1] * kv.y + q[d+2] * kv.z + q[d+3] * kv.w;
            }
            sum += __shfl_xor_sync(0xffffffffu, sum, 1);
            s[j] = sum;
        }

        if (t * 32 + 31 > row) {                  // diagonal tile: mask
            #pragma unroll
            for (int j = 0; j < 32; j++)
                if (t * 32 + j > row) s[j] = -1e30f;
        }

        float mt = mval;
        #pragma unroll
        for (int j = 0; j < 32; j++) mt = fmaxf(mt, s[j]);
        float alpha = exp2f(mval - mt);
        mval = mt;

        float ls = 0.f;
        #pragma unroll
        for (int j = 0; j < 32; j++) {
            s[j] = exp2f(s[j] - mt);
            ls += s[j];
        }
        lval = lval * alpha + ls;

        #pragma unroll
        for (int d = 0; d < 32; d++) acc[d] *= alpha;

        #pragma unroll
        for (int j = 0; j < 32; j++) {
            float p = s[j];
            #pragma unroll
            for (int d = 0; d < 32; d += 4) {
                float4 vv = *reinterpret_cast<const float4*>(&Vs[j][half * 32 + d]);
                acc[d]   += p * vv.x;
                acc[d+1] += p * vv.y;
                acc[d+2] += p * vv.z;
                acc[d+3] += p * vv.w;
            }
        }
        __syncthreads();
    }

    // Write context back in [b*s, d_model] layout
    const int b = bh >> 4;
    const int h = bh & 15;
    const float inv = 1.f / lval;
    float* optr = &g_ctx[((size_t)(b * SEQ + row)) * D_MODEL + h * D_HEAD + half * 32];
    #pragma unroll
    for (int d = 0; d < 32; d += 4) {
        float4 v = make_float4(acc[d] * inv, acc[d+1] * inv, acc[d+2] * inv, acc[d+3] * inv);
        *reinterpret_cast<float4*>(&optr[d]) = v;
    }
}

// ---------------------------------------------------------------------------
extern "C" void kernel_launch(void* const* d_in, const int* in_sizes, int n_in,
                              void* d_out, int out_size)
{
    const float* x   = (const float*)d_in[0];
    const float* W_q = (const float*)d_in[1];
    const float* b_q = (const float*)d_in[2];
    const float* W_k = (const float*)d_in[3];
    const float* b_k = (const float*)d_in[4];
    const float* W_v = (const float*)d_in[5];
    const float* b_v = (const float*)d_in[6];
    const float* W_o = (const float*)d_in[7];
    const float* b_o = (const float*)d_in[8];
    float* out = (float*)d_out;

    dim3 gProj(M_TOT / 128, D_MODEL / 128, 3);
    qkv_gemm_kernel<<<gProj, 256>>>(x, W_q, b_q, W_k, b_k, W_v, b_v);

    dim3 gAttn(SEQ / 64, BATCH * N_HEADS);
    flash_attn_kernel<<<gAttn, 128>>>();

    dim3 gOut(M_TOT / 128, D_MODEL / 128);
    out_gemm_kernel<<<gOut, 256>>>(W_o, b_o, out);
}

// round 6
// speedup vs baseline: 3.0996x; 2.4283x over previous
#include <cuda_runtime.h>
#include <cstdint>

#define D_MODEL 1024
#define N_HEADS 16
#define D_HEAD  64
#define BATCH   4
#define SEQ     2048
#define M_TOT   (BATCH * SEQ)   // 8192

// Scratch (device globals: allocation-free per harness rules)
__device__ float g_Q[(size_t)BATCH * N_HEADS * SEQ * D_HEAD];   // [b,h,s,dh]
__device__ float g_K[(size_t)BATCH * N_HEADS * SEQ * D_HEAD];
__device__ float g_V[(size_t)BATCH * N_HEADS * SEQ * D_HEAD];
__device__ float g_ctx[(size_t)M_TOT * D_MODEL];                // [b*s, d]

// ---------------------------------------------------------------------------
// tf32 helpers
// ---------------------------------------------------------------------------
__device__ __forceinline__ uint32_t f2tf32(float f) {
    uint32_t u;
    asm("cvt.rna.tf32.f32 %0, %1;" : "=r"(u) : "f"(f));
    return u;
}
__device__ __forceinline__ float f2tf32f(float f) {
    return __uint_as_float(f2tf32(f));
}

__device__ __forceinline__ void mma_tf32_16x8x8(
    float c[4], const uint32_t a[4], const uint32_t b[2])
{
    asm volatile(
        "mma.sync.aligned.m16n8k8.row.col.f32.tf32.tf32.f32 "
        "{%0,%1,%2,%3}, {%4,%5,%6,%7}, {%8,%9}, {%0,%1,%2,%3};"
        : "+f"(c[0]), "+f"(c[1]), "+f"(c[2]), "+f"(c[3])
        : "r"(a[0]), "r"(a[1]), "r"(a[2]), "r"(a[3]),
          "r"(b[0]), "r"(b[1]));
}

// ---------------------------------------------------------------------------
// tf32 tensor-core GEMM core: C_tile(128x128) = A(128xK) * W(Kx128), K=1024.
// (unchanged from R4 — validated)
// ---------------------------------------------------------------------------
#define A_STRIDE 20
#define B_STRIDE 136

__device__ __forceinline__ void gemm_tf32_core(
    const float* __restrict__ A,   // [M, 1024] row-major
    const float* __restrict__ W,   // [1024, 1024] row-major
    float acc[4][4][4], int bm, int bn)
{
    __shared__ __align__(16) float As[128][A_STRIDE];  // [m][k]
    __shared__ __align__(16) float Bs[16][B_STRIDE];   // [k][n]

    const int tid    = threadIdx.x;
    const int warp   = tid >> 5;
    const int lane   = tid & 31;
    const int gID    = lane >> 2;     // 0..7
    const int tID    = lane & 3;      // 0..3
    const int m_warp = (warp & 1) * 64;
    const int n_warp = (warp >> 1) * 32;

    for (int k0 = 0; k0 < 1024; k0 += 16) {
        #pragma unroll
        for (int i = 0; i < 2; i++) {
            int f   = tid * 2 + i;            // 0..511
            int row = f >> 2;                 // 0..127
            int kc  = (f & 3) << 2;           // 0,4,8,12
            float4 v = *reinterpret_cast<const float4*>(
                &A[(size_t)(bm + row) * 1024 + k0 + kc]);
            *reinterpret_cast<float4*>(&As[row][kc]) = v;
        }
        #pragma unroll
        for (int i = 0; i < 2; i++) {
            int f   = tid * 2 + i;
            int row = f >> 5;                 // 0..15
            int nc  = (f & 31) << 2;          // 0..124
            float4 v = *reinterpret_cast<const float4*>(
                &W[(size_t)(k0 + row) * 1024 + bn + nc]);
            *reinterpret_cast<float4*>(&Bs[row][nc]) = v;
        }
        __syncthreads();

        #pragma unroll
        for (int ks = 0; ks < 16; ks += 8) {
            uint32_t afrag[4][4];
            #pragma unroll
            for (int i = 0; i < 4; i++) {
                int r0 = m_warp + i * 16 + gID;
                afrag[i][0] = f2tf32(As[r0    ][ks + tID    ]);
                afrag[i][1] = f2tf32(As[r0 + 8][ks + tID    ]);
                afrag[i][2] = f2tf32(As[r0    ][ks + tID + 4]);
                afrag[i][3] = f2tf32(As[r0 + 8][ks + tID + 4]);
            }
            uint32_t bfrag[4][2];
            #pragma unroll
            for (int j = 0; j < 4; j++) {
                int c0 = n_warp + j * 8 + gID;
                bfrag[j][0] = f2tf32(Bs[ks + tID    ][c0]);
                bfrag[j][1] = f2tf32(Bs[ks + tID + 4][c0]);
            }
            #pragma unroll
            for (int i = 0; i < 4; i++)
                #pragma unroll
                for (int j = 0; j < 4; j++)
                    mma_tf32_16x8x8(acc[i][j], afrag[i], bfrag[j]);
        }
        __syncthreads();
    }
}

// ---------------------------------------------------------------------------
// QKV projection (unchanged from R4)
// ---------------------------------------------------------------------------
__global__ __launch_bounds__(256, 2)
void qkv_gemm_kernel(const float* __restrict__ x,
                     const float* __restrict__ Wq, const float* __restrict__ bq,
                     const float* __restrict__ Wk, const float* __restrict__ bk,
                     const float* __restrict__ Wv, const float* __restrict__ bv)
{
    const float* W; const float* bias; float* out;
    if      (blockIdx.z == 0) { W = Wq; bias = bq; out = g_Q; }
    else if (blockIdx.z == 1) { W = Wk; bias = bk; out = g_K; }
    else                      { W = Wv; bias = bv; out = g_V; }

    const int bm = blockIdx.x * 128;
    const int bn = blockIdx.y * 128;

    float acc[4][4][4];
    #pragma unroll
    for (int i = 0; i < 4; i++)
        #pragma unroll
        for (int j = 0; j < 4; j++)
            #pragma unroll
            for (int r = 0; r < 4; r++) acc[i][j][r] = 0.f;

    gemm_tf32_core(x, W, acc, bm, bn);

    const int warp   = threadIdx.x >> 5;
    const int lane   = threadIdx.x & 31;
    const int gID    = lane >> 2;
    const int tID    = lane & 3;
    const int m_warp = (warp & 1) * 64;
    const int n_warp = (warp >> 1) * 32;

    #pragma unroll
    for (int i = 0; i < 4; i++) {
        #pragma unroll
        for (int j = 0; j < 4; j++) {
            int n0 = bn + n_warp + j * 8 + tID * 2;
            int h  = n0 >> 6;
            int dh = n0 & 63;
            float b0v = bias[n0], b1v = bias[n0 + 1];
            #pragma unroll
            for (int rr = 0; rr < 2; rr++) {
                int m = bm + m_warp + i * 16 + gID + rr * 8;
                int b = m >> 11;
                int s = m & (SEQ - 1);
                float* dst = &out[(((size_t)(b * N_HEADS + h) * SEQ + s) * D_HEAD) + dh];
                float2 v = make_float2(acc[i][j][rr * 2] + b0v,
                                       acc[i][j][rr * 2 + 1] + b1v);
                *reinterpret_cast<float2*>(dst) = v;
            }
        }
    }
}

// ---------------------------------------------------------------------------
// Output projection (unchanged from R4)
// ---------------------------------------------------------------------------
__global__ __launch_bounds__(256, 2)
void out_gemm_kernel(const float* __restrict__ Wo,
                     const float* __restrict__ bo,
                     float* __restrict__ out)
{
    const int bm = blockIdx.x * 128;
    const int bn = blockIdx.y * 128;

    float acc[4][4][4];
    #pragma unroll
    for (int i = 0; i < 4; i++)
        #pragma unroll
        for (int j = 0; j < 4; j++)
            #pragma unroll
            for (int r = 0; r < 4; r++) acc[i][j][r] = 0.f;

    gemm_tf32_core(g_ctx, Wo, acc, bm, bn);

    const int warp   = threadIdx.x >> 5;
    const int lane   = threadIdx.x & 31;
    const int gID    = lane >> 2;
    const int tID    = lane & 3;
    const int m_warp = (warp & 1) * 64;
    const int n_warp = (warp >> 1) * 32;

    #pragma unroll
    for (int i = 0; i < 4; i++) {
        #pragma unroll
        for (int j = 0; j < 4; j++) {
            int n0 = bn + n_warp + j * 8 + tID * 2;
            float b0v = bo[n0], b1v = bo[n0 + 1];
            #pragma unroll
            for (int rr = 0; rr < 2; rr++) {
                int m = bm + m_warp + i * 16 + gID + rr * 8;
                float2 v = make_float2(acc[i][j][rr * 2] + b0v,
                                       acc[i][j][rr * 2 + 1] + b1v);
                *reinterpret_cast<float2*>(&out[(size_t)m * D_MODEL + n0]) = v;
            }
        }
    }
}

// ---------------------------------------------------------------------------
// Causal flash attention with tf32 tensor cores.
// Block = 128 threads / 4 warps; Q tile = 64 rows (16 per warp, one m16).
// KV tiles of 32 keys staged in smem pre-converted to tf32. Online softmax
// in C-fragment registers; P round-trips through per-warp smem slab for
// A-fragment layout (warp-local: __syncwarp only).
// grid = (SEQ/64, BATCH*N_HEADS)
// ---------------------------------------------------------------------------
__global__ __launch_bounds__(128, 4)
void flash_attn_tc_kernel()
{
    __shared__ __align__(16) float Qs[64][68];  // 4g+t bank map: conflict-free
    __shared__ __align__(16) float Ks[32][68];  // rows vary gID -> 4g+t: free
    __shared__ __align__(16) float Vs[32][72];  // rows vary tID -> 8t+g: free
    __shared__ __align__(16) float Ps[64][36];  // 4g+t: free

    const int tid  = threadIdx.x;
    const int warp = tid >> 5;
    const int lane = tid & 31;
    const int gID  = lane >> 2;     // 0..7
    const int tID  = lane & 3;      // 0..3
    const int qt   = blockIdx.x;    // 0..31
    const int bh   = blockIdx.y;    // 0..63
    const int qbase = qt << 6;
    const int r0   = warp << 4;     // local row base for this warp

    const float sc = 0.125f * 1.44269504088896340736f;  // 1/sqrt(64)*log2(e)

    // Stage Q tile: 64x64, scaled + tf32-rounded. 2 threads/row.
    {
        const float* qsrc = &g_Q[((size_t)bh * SEQ + qbase) * D_HEAD];
        int row  = tid >> 1;
        int colb = (tid & 1) * 32;
        #pragma unroll
        for (int i = 0; i < 8; i++) {
            float4 v = *reinterpret_cast<const float4*>(
                &qsrc[(size_t)row * 64 + colb + i * 4]);
            Qs[row][colb + i*4 + 0] = f2tf32f(v.x * sc);
            Qs[row][colb + i*4 + 1] = f2tf32f(v.y * sc);
            Qs[row][colb + i*4 + 2] = f2tf32f(v.z * sc);
            Qs[row][colb + i*4 + 3] = f2tf32f(v.w * sc);
        }
    }

    float m0 = -1e30f, m1 = -1e30f, l0 = 0.f, l1 = 0.f;
    float co[8][4];
    #pragma unroll
    for (int j = 0; j < 8; j++)
        #pragma unroll
        for (int r = 0; r < 4; r++) co[j][r] = 0.f;

    const float* Kb = &g_K[(size_t)bh * SEQ * D_HEAD];
    const float* Vb = &g_V[(size_t)bh * SEQ * D_HEAD];

    __syncthreads();   // Q visible to all warps

    const int ntiles = 2 * qt + 2;
    for (int t = 0; t < ntiles; t++) {
        // Stage K,V tile (32x64 each), tf32-rounded. 4 threads/row.
        {
            int row  = tid >> 2;
            int colb = (tid & 3) * 16;
            const float* ks = Kb + ((size_t)t * 32 + row) * 64 + colb;
            const float* vs = Vb + ((size_t)t * 32 + row) * 64 + colb;
            #pragma unroll
            for (int i = 0; i < 4; i++) {
                float4 kv = *reinterpret_cast<const float4*>(&ks[i * 4]);
                Ks[row][colb + i*4 + 0] = f2tf32f(kv.x);
                Ks[row][colb + i*4 + 1] = f2tf32f(kv.y);
                Ks[row][colb + i*4 + 2] = f2tf32f(kv.z);
                Ks[row][colb + i*4 + 3] = f2tf32f(kv.w);
                float4 vv = *reinterpret_cast<const float4*>(&vs[i * 4]);
                Vs[row][colb + i*4 + 0] = f2tf32f(vv.x);
                Vs[row][colb + i*4 + 1] = f2tf32f(vv.y);
                Vs[row][colb + i*4 + 2] = f2tf32f(vv.z);
                Vs[row][colb + i*4 + 3] = f2tf32f(vv.w);
            }
        }
        __syncthreads();

        // ---- S = Q @ K^T  (m16 x n32, k=64) ----
        float sfrag[4][4];
        #pragma unroll
        for (int j = 0; j < 4; j++)
            #pragma unroll
            for (int r = 0; r < 4; r++) sfrag[j][r] = 0.f;

        #pragma unroll
        for (int k8 = 0; k8 < 64; k8 += 8) {
            uint32_t a[4];
            a[0] = __float_as_uint(Qs[r0 + gID    ][k8 + tID    ]);
            a[1] = __float_as_uint(Qs[r0 + gID + 8][k8 + tID    ]);
            a[2] = __float_as_uint(Qs[r0 + gID    ][k8 + tID + 4]);
            a[3] = __float_as_uint(Qs[r0 + gID + 8][k8 + tID + 4]);
            #pragma unroll
            for (int j = 0; j < 4; j++) {
                uint32_t b[2];
                b[0] = __float_as_uint(Ks[j*8 + gID][k8 + tID    ]);
                b[1] = __float_as_uint(Ks[j*8 + gID][k8 + tID + 4]);
                mma_tf32_16x8x8(sfrag[j], a, b);
            }
        }

        // ---- causal mask (only last two tiles) ----
        const int rg0 = qbase + r0 + gID;
        const int rg1 = rg0 + 8;
        if (t >= 2 * qt) {
            #pragma unroll
            for (int j = 0; j < 4; j++) {
                int key = t * 32 + j * 8 + tID * 2;
                if (key     > rg0) sfrag[j][0] = -1e30f;
                if (key + 1 > rg0) sfrag[j][1] = -1e30f;
                if (key     > rg1) sfrag[j][2] = -1e30f;
                if (key + 1 > rg1) sfrag[j][3] = -1e30f;
            }
        }

        // ---- online softmax ----
        float tm0 = -1e30f, tm1 = -1e30f;
        #pragma unroll
        for (int j = 0; j < 4; j++) {
            tm0 = fmaxf(tm0, fmaxf(sfrag[j][0], sfrag[j][1]));
            tm1 = fmaxf(tm1, fmaxf(sfrag[j][2], sfrag[j][3]));
        }
        tm0 = fmaxf(tm0, __shfl_xor_sync(0xffffffffu, tm0, 1));
        tm0 = fmaxf(tm0, __shfl_xor_sync(0xffffffffu, tm0, 2));
        tm1 = fmaxf(tm1, __shfl_xor_sync(0xffffffffu, tm1, 1));
        tm1 = fmaxf(tm1, __shfl_xor_sync(0xffffffffu, tm1, 2));

        float mn0 = fmaxf(m0, tm0), mn1 = fmaxf(m1, tm1);
        float al0 = exp2f(m0 - mn0), al1 = exp2f(m1 - mn1);
        m0 = mn0; m1 = mn1;

        float ls0 = 0.f, ls1 = 0.f;
        #pragma unroll
        for (int j = 0; j < 4; j++) {
            float p0 = f2tf32f(exp2f(sfrag[j][0] - m0));
            float p1 = f2tf32f(exp2f(sfrag[j][1] - m0));
            float p2 = f2tf32f(exp2f(sfrag[j][2] - m1));
            float p3 = f2tf32f(exp2f(sfrag[j][3] - m1));
            ls0 += p0 + p1;
            ls1 += p2 + p3;
            int col = j * 8 + tID * 2;
            *reinterpret_cast<float2*>(&Ps[r0 + gID    ][col]) = make_float2(p0, p1);
            *reinterpret_cast<float2*>(&Ps[r0 + gID + 8][col]) = make_float2(p2, p3);
        }
        ls0 += __shfl_xor_sync(0xffffffffu, ls0, 1);
        ls0 += __shfl_xor_sync(0xffffffffu, ls0, 2);
        ls1 += __shfl_xor_sync(0xffffffffu, ls1, 1);
        ls1 += __shfl_xor_sync(0xffffffffu, ls1, 2);
        l0 = l0 * al0 + ls0;
        l1 = l1 * al1 + ls1;

        // rescale accumulators
        #pragma unroll
        for (int j = 0; j < 8; j++) {
            co[j][0] *= al0; co[j][1] *= al0;
            co[j][2] *= al1; co[j][3] *= al1;
        }

        __syncwarp();   // P stores visible within warp

        // ---- ctx += P @ V  (m16 x n64, k=32) ----
        #pragma unroll
        for (int k8 = 0; k8 < 32; k8 += 8) {
            uint32_t a[4];
            a[0] = __float_as_uint(Ps[r0 + gID    ][k8 + tID    ]);
            a[1] = __float_as_uint(Ps[r0 + gID + 8][k8 + tID    ]);
            a[2] = __float_as_uint(Ps[r0 + gID    ][k8 + tID + 4]);
            a[3] = __float_as_uint(Ps[r0 + gID + 8][k8 + tID + 4]);
            #pragma unroll
            for (int jn = 0; jn < 8; jn++) {
                uint32_t b[2];
                b[0] = __float_as_uint(Vs[k8 + tID    ][jn*8 + gID]);
                b[1] = __float_as_uint(Vs[k8 + tID + 4][jn*8 + gID]);
                mma_tf32_16x8x8(co[jn], a, b);
            }
        }
        __syncthreads();   // before next tile overwrites Ks/Vs
    }

    // ---- normalize and write context: [b*s, d_model] ----
    const float inv0 = 1.f / l0;
    const float inv1 = 1.f / l1;
    const int b = bh >> 4;
    const int h = bh & 15;
    const int grow0 = qbase + r0 + gID;
    const int grow1 = grow0 + 8;
    #pragma unroll
    for (int jn = 0; jn < 8; jn++) {
        int col = h * 64 + jn * 8 + tID * 2;
        *reinterpret_cast<float2*>(&g_ctx[(size_t)(b * SEQ + grow0) * D_MODEL + col]) =
            make_float2(co[jn][0] * inv0, co[jn][1] * inv0);
        *reinterpret_cast<float2*>(&g_ctx[(size_t)(b * SEQ + grow1) * D_MODEL + col]) =
            make_float2(co[jn][2] * inv1, co[jn][3] * inv1);
    }
}

// ---------------------------------------------------------------------------
extern "C" void kernel_launch(void* const* d_in, const int* in_sizes, int n_in,
                              void* d_out, int out_size)
{
    const float* x   = (const float*)d_in[0];
    const float* W_q = (const float*)d_in[1];
    const float* b_q = (const float*)d_in[2];
    const float* W_k = (const float*)d_in[3];
    const float* b_k = (const float*)d_in[4];
    const float* W_v = (const float*)d_in[5];
    const float* b_v = (const float*)d_in[6];
    const float* W_o = (const float*)d_in[7];
    const float* b_o = (const float*)d_in[8];
    float* out = (float*)d_out;

    dim3 gProj(M_TOT / 128, D_MODEL / 128, 3);
    qkv_gemm_kernel<<<gProj, 256>>>(x, W_q, b_q, W_k, b_k, W_v, b_v);

    dim3 gAttn(SEQ / 64, BATCH * N_HEADS);
    flash_attn_tc_kernel<<<gAttn, 128>>>();

    dim3 gOut(M_TOT / 128, D_MODEL / 128);
    out_gemm_kernel<<<gOut, 256>>>(W_o, b_o, out);
}